// round 14
// baseline (speedup 1.0000x reference)
#include <cuda_runtime.h>
#include <stdint.h>

#define IN_DIM   4096
#define OUT_DIM  1024
#define RB       96      // x rows per block (3 per lane: L, L+32, L+64)
#define KT       512     // K columns per phase
#define NPH      8       // IN_DIM / KT
#define TPB      1024
#define OPW      8       // outputs per warp
#define OSPLIT   4       // output groups
#define OPB      (OUT_DIM / OSPLIT)   // 256 outputs per block
#define NSLICE   (NPH * OSPLIT)       // 32 (phase, outgroup) slices
#define SLICE_CAP 2048   // entries per slice (avg ~1280, std ~36)
#define XS_STRIDE 513    // floats; 513 % 32 == 1 -> bank = (row+col)%32, conflict-free
#define ROWA_BYTES (32 * XS_STRIDE * 4)   // 65664  : row L -> L+32
#define ROWB_BYTES (64 * XS_STRIDE * 4)   // 131328 : row L -> L+64
#define TAB_OFF   (RB * XS_STRIDE * 4)    // 196992 (16B aligned)
#define OFF_OFF   (TAB_OFF + SLICE_CAP * 8)          // 213376
#define SMEM_BYTES (OFF_OFF + (OPB + 4) * 4)         // 214416
#define OSTRIDE   260    // floats, epilogue staging stride (16B aligned)

// Phase-major packed sparse table (rebuilt every launch; deterministic).
// Slice s = p*OSPLIT + og: entries of phase p for outputs [og*256, og*256+256).
// Entry = { byte offset of col within its KT-segment, fp32 value bits }.
__device__ int  g_cnt[NPH * OUT_DIM];
__device__ int  g_soff[NSLICE][OPB + 1];
__device__ int2 g_ptab[NSLICE * SLICE_CAP];

// ---------------------------------------------------------------------------
// Prep 1: nonzero count per (output o, phase q). Warp q owns cols [q*512,+512).
// ---------------------------------------------------------------------------
__global__ void __launch_bounds__(256) count_kernel(const float* __restrict__ Phi) {
    const int o = blockIdx.x, t = threadIdx.x, q = t >> 5, u = t & 31;
    const float* row = Phi + (size_t)o * IN_DIM;
    int cnt = 0;
#pragma unroll
    for (int k = 0; k < 16; k++) cnt += (row[q * KT + k * 32 + u] != 0.0f);
#pragma unroll
    for (int d = 16; d; d >>= 1) cnt += __shfl_down_sync(0xffffffffu, cnt, d);
    if (u == 0) g_cnt[q * OUT_DIM + o] = cnt;
}

// ---------------------------------------------------------------------------
// Prep 2: exclusive scan of counts within each (phase, outgroup) slice.
// ---------------------------------------------------------------------------
__global__ void __launch_bounds__(OPB) scan_kernel() {
    const int s = blockIdx.x;              // s = p*OSPLIT + og
    const int p = s >> 2, og = s & 3, t = threadIdx.x;
    __shared__ int sh[OPB];
    int c = g_cnt[p * OUT_DIM + og * OPB + t];
    sh[t] = c;
    __syncthreads();
#pragma unroll
    for (int d = 1; d < OPB; d <<= 1) {
        int v = (t >= d) ? sh[t - d] : 0;
        __syncthreads();
        sh[t] += v;
        __syncthreads();
    }
    g_soff[s][t] = min(sh[t] - c, SLICE_CAP);
    if (t == OPB - 1) g_soff[s][OPB] = min(sh[t], SLICE_CAP);
}

// ---------------------------------------------------------------------------
// Prep 3: fill packed table (deterministic lane-k order).
// ---------------------------------------------------------------------------
__global__ void __launch_bounds__(256) fill_kernel(const float* __restrict__ Phi) {
    const int o = blockIdx.x, t = threadIdx.x, q = t >> 5, u = t & 31;
    const int og = o >> 8;                 // o / OPB
    const int ol = o & (OPB - 1);
    const int s  = q * OSPLIT + og;
    const float* row = Phi + (size_t)o * IN_DIM;

    float rv[16];
    int cnt = 0;
#pragma unroll
    for (int k = 0; k < 16; k++) { rv[k] = row[q * KT + k * 32 + u]; cnt += (rv[k] != 0.0f); }

    int ex = cnt;
#pragma unroll
    for (int d = 1; d < 32; d <<= 1) {
        int v = __shfl_up_sync(0xffffffffu, ex, d);
        if (u >= d) ex += v;
    }
    ex -= cnt;   // exclusive prefix over lanes

    int dst = g_soff[s][ol] + ex;
#pragma unroll
    for (int k = 0; k < 16; k++) {
        float v = rv[k];
        if (v != 0.0f) {
            if (dst < SLICE_CAP)
                g_ptab[s * SLICE_CAP + dst] = make_int2((k * 32 + u) * 4, __float_as_int(v));
            dst++;
        }
    }
}

// ---------------------------------------------------------------------------
// Main: sparse out = x @ Phi^T. Block: 96 x-rows (lane L -> rows L, L+32,
// L+64 via immediate smem offsets), 256 outputs (warp w -> 8 contiguous),
// 8 K-phases of 512 cols. Each table entry feeds 3 FMAs.
// blockIdx: low 2 bits = output group (4 siblings share x rows -> L2 reuse).
// ---------------------------------------------------------------------------
__global__ void __launch_bounds__(TPB, 1) spjl_kernel(
    const float* __restrict__ x, float* __restrict__ out, int nrows) {
    extern __shared__ float xs[];                       // x tile [96 * 513]
    int2* st_tab = (int2*)((char*)xs + TAB_OFF);
    int*  st_off = (int*)((char*)xs + OFF_OFF);

    const int tid = threadIdx.x;
    const int w   = tid >> 5;
    const int L   = tid & 31;
    const int rg  = blockIdx.x >> 2;
    const int og  = blockIdx.x & 3;
    const size_t n0 = (size_t)rg * RB;
    const int olb = w * OPW;                            // warp's first local output

    float acc0[OPW], acc1[OPW], acc2[OPW];
#pragma unroll
    for (int io = 0; io < OPW; io++) { acc0[io] = 0.0f; acc1[io] = 0.0f; acc2[io] = 0.0f; }

    const char* xrow = (const char*)(xs + L * XS_STRIDE);

    for (int p = 0; p < NPH; p++) {
        const int s = p * OSPLIT + og;
        const int len = g_soff[s][OPB];
        __syncthreads();   // previous phase readers done before overwrite

        // Stage x tile: 96 rows x 512 cols, float2 units (coalesced, conflict-free).
#pragma unroll
        for (int it = 0; it < (RB * KT / 2) / TPB; it++) {
            int idx2 = tid + it * TPB;
            int rr   = idx2 >> 8;          // 256 float2 per row
            int c2   = idx2 & 255;
            size_t gr = n0 + rr;
            float2 v = make_float2(0.0f, 0.0f);
            if (gr < (size_t)nrows)
                v = *(const float2*)(x + gr * IN_DIM + (size_t)p * KT + c2 * 2);
            xs[rr * XS_STRIDE + c2 * 2]     = v.x;
            xs[rr * XS_STRIDE + c2 * 2 + 1] = v.y;
        }
        // Stage table slice + offsets (coalesced).
        if (tid <= OPB) st_off[tid] = g_soff[s][tid];
        for (int i = tid; i < len; i += TPB) st_tab[i] = g_ptab[s * SLICE_CAP + i];
        __syncthreads();

        int jb = st_off[olb];
#pragma unroll
        for (int io = 0; io < OPW; io++) {
            const int je = st_off[olb + io + 1];
            float a0 = acc0[io], a1 = acc1[io], a2 = acc2[io];
#pragma unroll 4
            for (int j = jb; j < je; j++) {
                int2 e = st_tab[j];                        // warp-uniform broadcast
                float phv = __int_as_float(e.y);
                a0 = fmaf(phv, *(const float*)(xrow + e.x), a0);
                a1 = fmaf(phv, *(const float*)(xrow + ROWA_BYTES + e.x), a1);
                a2 = fmaf(phv, *(const float*)(xrow + ROWB_BYTES + e.x), a2);
            }
            acc0[io] = a0; acc1[io] = a1; acc2[io] = a2;
            jb = je;
        }
    }

    __syncthreads();
    // Stage results (alias x tile), stride OSTRIDE, then coalesced float4 STG.
#pragma unroll
    for (int io = 0; io < OPW; io++) {
        xs[L        * OSTRIDE + olb + io] = acc0[io];
        xs[(L + 32) * OSTRIDE + olb + io] = acc1[io];
        xs[(L + 64) * OSTRIDE + olb + io] = acc2[io];
    }
    __syncthreads();
#pragma unroll
    for (int it = 0; it < (RB * OPB / 4) / TPB; it++) {
        int i4  = tid + it * TPB;
        int row = i4 >> 6;                 // 64 float4 per row
        int c4  = i4 & 63;
        size_t gr = n0 + row;
        if (gr < (size_t)nrows) {
            float4 v = *(const float4*)(xs + row * OSTRIDE + c4 * 4);
            *(float4*)(out + gr * OUT_DIM + og * OPB + c4 * 4) = v;
        }
    }
}

extern "C" void kernel_launch(void* const* d_in, const int* in_sizes, int n_in,
                              void* d_out, int out_size) {
    const float* x   = (const float*)d_in[0];   // [N, 4096] fp32
    const float* Phi = (const float*)d_in[1];   // [1024, 4096] fp32
    float* out = (float*)d_out;                 // [N, 1024] fp32

    const int nrows = in_sizes[0] / IN_DIM;              // 16384
    const int grid  = ((nrows + RB - 1) / RB) * OSPLIT;  // 171 * 4 = 684

    cudaFuncSetAttribute(spjl_kernel,
                         cudaFuncAttributeMaxDynamicSharedMemorySize, SMEM_BYTES);

    count_kernel<<<OUT_DIM, 256>>>(Phi);
    scan_kernel<<<NSLICE, OPB>>>();
    fill_kernel<<<OUT_DIM, 256>>>(Phi);
    spjl_kernel<<<grid, TPB, SMEM_BYTES>>>(x, out, nrows);
}